// round 1
// baseline (speedup 1.0000x reference)
#include <cuda_runtime.h>
#include <math.h>

#define NIMG   256
#define HW     1024
#define CH_OUT 64
#define PLANE  (CH_OUT*HW)     // 65536
#define TOT    (NIMG*PLANE)    // 16777216

// Scratch (allocation-free rule: __device__ globals). A/B reused across layers.
__device__ float g_A[TOT];
__device__ float g_B[TOT];
__device__ float g_O1[TOT];
__device__ float g_hdump[4*PLANE];

__device__ __forceinline__ float sigmoidf_(float x) { return 1.0f/(1.0f+expf(-x)); }

// Fused conv3x3 (pad 1) + minGRU pointwise epilogue.
// Grid: 256 images * 8 oc-tiles * 4 row-bands. Block: 128 threads.
// Block computes 16 output channels = 8 gate channels (tile*8..tile*8+7) and
// their paired hidden channels (+64), over an 8-row x 32-col band.
// Thread tile: 2 gate/hidden channel pairs x 8 pixels (one row strip).
template<int IC>
__global__ void __launch_bounds__(128)
conv_gru(const float* __restrict__ xin,   // (256, IC, 32, 32)
         const float* __restrict__ wt,    // (128, IC, 3, 3)
         const float* __restrict__ bias,  // (128)
         float* __restrict__ Aout,        // (256, 64, 32, 32):  1 - z
         float* __restrict__ Bout)        // z * g(hidden)
{
    __shared__ float w_s[IC*144];        // [ic][k=9][slot=16]
    __shared__ float in_s[8*10*36];      // [ic8][row10][col36 (pitch-padded)]

    const int blk  = blockIdx.x;
    const int band = blk & 3;
    const int tile = (blk >> 2) & 7;
    const int n    = blk >> 5;
    const int tid  = threadIdx.x;

    // Stage weights: slot j<8 -> gate oc = tile*8+j ; j>=8 -> hidden oc = 64+tile*8+(j-8)
    for (int idx = tid; idx < IC*144; idx += 128) {
        int slot = idx / (IC*9);
        int rem  = idx - slot*(IC*9);          // ic*9 + k
        int oc   = (slot < 8) ? (tile*8 + slot) : (64 + tile*8 + slot - 8);
        w_s[rem*16 + slot] = wt[oc*IC*9 + rem];
    }

    const int ocg   = tid >> 5;        // 0..3 : which channel-pair group (one warp each)
    const int lane  = tid & 31;
    const int trow  = lane >> 2;       // 0..7 : row within band
    const int strip = lane & 3;        // 0..3 : 8-col strip
    const int c0    = strip * 8;
    const int row0  = band * 8;

    float acc[4][8];                   // [2 gate + 2 hidden][8 px]
    #pragma unroll
    for (int j = 0; j < 4; j++)
        #pragma unroll
        for (int p = 0; p < 8; p++) acc[j][p] = 0.f;

    for (int icb = 0; icb < IC; icb += 8) {
        __syncthreads();
        // Load 8 input channels, rows row0-1..row0+8, cols -1..32 (pitch 36, zero pad)
        for (int idx = tid; idx < 2880; idx += 128) {
            int ch = idx / 360;
            int r  = (idx - ch*360) / 36;
            int cc = idx - ch*360 - r*36;
            int gr = row0 + r - 1;
            int gc = cc - 1;
            float v = 0.f;
            if ((unsigned)gr < 32u && (unsigned)gc < 32u)
                v = xin[((n*IC + icb + ch) << 10) + (gr << 5) + gc];
            in_s[idx] = v;
        }
        __syncthreads();

        #pragma unroll
        for (int ic = 0; ic < 8; ic++) {
            const float* wp = w_s + (icb + ic) * 144;
            const float* ip = in_s + ic*360 + trow*36 + c0;
            #pragma unroll
            for (int dr = 0; dr < 3; dr++) {
                float in[10];
                const float4 v0 = *(const float4*)(ip + dr*36);
                const float4 v1 = *(const float4*)(ip + dr*36 + 4);
                in[0]=v0.x; in[1]=v0.y; in[2]=v0.z; in[3]=v0.w;
                in[4]=v1.x; in[5]=v1.y; in[6]=v1.z; in[7]=v1.w;
                in[8]=ip[dr*36 + 8]; in[9]=ip[dr*36 + 9];
                #pragma unroll
                for (int j = 0; j < 4; j++) {
                    const int slot = (j < 2) ? (2*ocg + j) : (8 + 2*ocg + j - 2);
                    const float w0 = wp[(dr*3 + 0)*16 + slot];
                    const float w1 = wp[(dr*3 + 1)*16 + slot];
                    const float w2 = wp[(dr*3 + 2)*16 + slot];
                    #pragma unroll
                    for (int p = 0; p < 8; p++)
                        acc[j][p] = fmaf(w0, in[p],
                                     fmaf(w1, in[p+1],
                                      fmaf(w2, in[p+2], acc[j][p])));
                }
            }
        }
    }

    // Epilogue: fuse gate/hidden into scan coefficients a = 1-z, b = z*g(h)
    const int cg = tile*8 + 2*ocg;   // gate channel base in [0,64)
    #pragma unroll
    for (int j = 0; j < 2; j++) {
        const float bg = bias[cg + j];
        const float bh = bias[64 + cg + j];
        const int off = ((n*64 + cg + j) << 10) + ((row0 + trow) << 5) + c0;
        float av[8], bv[8];
        #pragma unroll
        for (int p = 0; p < 8; p++) {
            float z  = sigmoidf_(acc[j][p] + bg);
            float hv = acc[2 + j][p] + bh;
            float gg = (hv >= 0.f) ? (hv + 0.5f) : sigmoidf_(hv);
            av[p] = 1.0f - z;
            bv[p] = z * gg;
        }
        *(float4*)(Aout + off)     = *(float4*)(av);
        *(float4*)(Aout + off + 4) = *(float4*)(av + 4);
        *(float4*)(Bout + off)     = *(float4*)(bv);
        *(float4*)(Bout + off + 4) = *(float4*)(bv + 4);
    }
}

// Sequential minGRU scan over S=64. One thread per (batch, c*h*w) lane.
// h_t = a_t * h_{t-1} + b_t, h_{-1} = 0.5 (g(0)). Coalesced over chw at each t.
__global__ void __launch_bounds__(256)
scan_k(const float* __restrict__ A, const float* __restrict__ Bv,
       float* __restrict__ out, float* __restrict__ hlast)
{
    int idx = blockIdx.x * blockDim.x + threadIdx.x;   // 262144 lanes
    int b   = idx >> 16;
    int chw = idx & 65535;
    size_t base = (size_t)(b << 6) * PLANE + chw;
    float h = 0.5f;
    #pragma unroll 8
    for (int t = 0; t < 64; t++) {
        size_t off = base + (size_t)t * PLANE;
        h = fmaf(A[off], h, Bv[off]);
        out[off] = h;
    }
    hlast[idx] = h;
}

extern "C" void kernel_launch(void* const* d_in, const int* in_sizes, int n_in,
                              void* d_out, int out_size) {
    const float* x  = (const float*)d_in[0];
    const float* w1 = (const float*)d_in[1];
    const float* b1 = (const float*)d_in[2];
    const float* w2 = (const float*)d_in[3];
    const float* b2 = (const float*)d_in[4];
    float* out = (float*)d_out;

    float *pA, *pB, *pO1, *pH;
    cudaGetSymbolAddress((void**)&pA,  g_A);
    cudaGetSymbolAddress((void**)&pB,  g_B);
    cudaGetSymbolAddress((void**)&pO1, g_O1);
    cudaGetSymbolAddress((void**)&pH,  g_hdump);

    // Output layout: out2 (16777216) | h1 (262144) | h2 (262144)
    bool full = (out_size >= TOT + 8*PLANE);
    float* h1 = full ? (out + TOT)            : pH;
    float* h2 = full ? (out + TOT + 4*PLANE)  : pH;

    conv_gru<32><<<8192, 128>>>(x, w1, b1, pA, pB);
    scan_k<<<1024, 256>>>(pA, pB, pO1, h1);
    conv_gru<64><<<8192, 128>>>(pO1, w2, b2, pA, pB);
    scan_k<<<1024, 256>>>(pA, pB, out, h2);
}

// round 3
// speedup vs baseline: 2.5404x; 2.5404x over previous
#include <cuda_runtime.h>
#include <math.h>
#include <stdint.h>

#define NIMG  256
#define PLANE 65536
#define TOT   16777216

// Scratch (__device__ globals per allocation rules)
__device__ float    g_A[TOT];
__device__ float    g_B[TOT];
__device__ float    g_O1[TOT];
__device__ float    g_hdump[4*PLANE];
__device__ uint32_t g_Wpk1[9*4608];    // layer1 packed tf32 weights [chunk][128][36]
__device__ uint32_t g_Wpk2[18*4608];   // layer2

__device__ __forceinline__ uint32_t tf32r(float v) {
    uint32_t t; asm("cvt.rna.tf32.f32 %0, %1;" : "=r"(t) : "f"(v)); return t;
}
__device__ __forceinline__ float sigm(float x) { return 1.f/(1.f+__expf(-x)); }

// Pre-pack weights to tf32 bits, chunk layout [m][oc][36] (cols 0..31 = ic, pitch pad 4)
__global__ void pack_w(const float* __restrict__ w, uint32_t* __restrict__ dst, int IC) {
    int idx = blockIdx.x * 256 + threadIdx.x;
    int total = (IC * 9 / 32) * 4608;
    if (idx >= total) return;
    int m = idx / 4608, rem = idx - m * 4608, oc = rem / 36, j = rem - oc * 36;
    uint32_t v = 0;
    if (j < 32) {
        int tap = (IC == 32) ? m : (m >> 1);
        int icb = (IC == 32) ? 0 : ((m & 1) << 5);
        v = tf32r(w[(oc * IC + icb + j) * 9 + tap]);
    }
    dst[idx] = v;
}

// Conv3x3 (pad1) as implicit GEMM on tensor cores (mma.sync tf32) + fused minGRU epilogue.
// Grid 1024 = 256 images x 4 bands(8 rows). 512 threads = 16 warps, warp tile 32oc x 64px.
// Warp M-frags = gate oc (16*mw+g[,+8]) and paired hidden oc (+64): epilogue in registers.
template<int IC>
__global__ void __launch_bounds__(512, 1)
conv_mma(const float* __restrict__ xin, const uint32_t* __restrict__ wpk,
         const float* __restrict__ bias,
         float* __restrict__ Aout, float* __restrict__ Bout)
{
    extern __shared__ float sm[];
    uint32_t* ws = (uint32_t*)sm;        // weight chunk [128][36] tf32 bits
    float* tile  = sm + 4608;            // padded input [IC][10 rows][36 cols]

    const int tid = threadIdx.x;
    const int wv = tid >> 5, lane = tid & 31;
    const int g = lane >> 2, tig = lane & 3;
    const int mw = wv & 3, nw = wv >> 2;
    const int n0 = nw * 64;
    const int blk = blockIdx.x, band = blk & 3, n = blk >> 2, r0 = band * 8;

    // Padded input tile: rows r0-1..r0+8 (10), cols -1..33 (36, incl. pitch pad), zero-fill
    for (int idx = tid; idx < IC * 360; idx += 512) {
        int ic = idx / 360, rem = idx - ic * 360, r = rem / 36, c = rem - r * 36;
        int gr = r0 + r - 1, gc = c - 1;
        float v = 0.f;
        if ((unsigned)gr < 32u && (unsigned)gc < 32u)
            v = xin[((n * IC + ic) << 10) + (gr << 5) + gc];
        tile[idx] = v;
    }

    float acc[2][8][4];
    #pragma unroll
    for (int f = 0; f < 2; f++)
        #pragma unroll
        for (int nt = 0; nt < 8; nt++)
            #pragma unroll
            for (int j = 0; j < 4; j++) acc[f][nt][j] = 0.f;

    const int NCH = IC * 9 / 32;
    const int ro = mw * 16 + g;
    for (int m = 0; m < NCH; m++) {
        __syncthreads();
        {   // stage weight chunk (18KB, L2-hot)
            const float4* src = (const float4*)(wpk + m * 4608);
            float4* d4 = (float4*)ws;
            #pragma unroll 3
            for (int i = tid; i < 1152; i += 512) d4[i] = src[i];
        }
        __syncthreads();
        const int tap = (IC == 32) ? m : (m >> 1);
        const int icb = (IC == 32) ? 0 : ((m & 1) << 5);
        const int dr = tap / 3, dc = tap - dr * 3;
        const int soff = dr * 36 + dc;

        #pragma unroll
        for (int s = 0; s < 4; s++) {
            const int kk = s * 8 + tig;
            uint32_t a[2][4];
            a[0][0] = ws[ro * 36 + kk];          a[0][1] = ws[(ro + 8) * 36 + kk];
            a[0][2] = ws[ro * 36 + kk + 4];      a[0][3] = ws[(ro + 8) * 36 + kk + 4];
            a[1][0] = ws[(ro + 64) * 36 + kk];   a[1][1] = ws[(ro + 72) * 36 + kk];
            a[1][2] = ws[(ro + 64) * 36 + kk + 4]; a[1][3] = ws[(ro + 72) * 36 + kk + 4];

            uint32_t b[8][2];
            const float* tb = tile + (icb + kk) * 360 + soff;
            #pragma unroll
            for (int nt = 0; nt < 8; nt++) {
                int px = n0 + nt * 8 + g;
                int sp = (px >> 5) * 36 + (px & 31);
                b[nt][0] = tf32r(tb[sp]);
                b[nt][1] = tf32r(tb[sp + 1440]);   // +4 input channels
            }
            #pragma unroll
            for (int f = 0; f < 2; f++)
                #pragma unroll
                for (int nt = 0; nt < 8; nt++)
                    asm volatile(
                        "mma.sync.aligned.m16n8k8.row.col.f32.tf32.tf32.f32 "
                        "{%0,%1,%2,%3}, {%4,%5,%6,%7}, {%8,%9}, {%0,%1,%2,%3};"
                        : "+f"(acc[f][nt][0]), "+f"(acc[f][nt][1]),
                          "+f"(acc[f][nt][2]), "+f"(acc[f][nt][3])
                        : "r"(a[f][0]), "r"(a[f][1]), "r"(a[f][2]), "r"(a[f][3]),
                          "r"(b[nt][0]), "r"(b[nt][1]));
        }
    }

    // Fused minGRU epilogue: a = 1 - sigmoid(gate), b = sigmoid(gate) * g(hidden)
    const float bg0 = __ldg(bias + ro),      bg1 = __ldg(bias + ro + 8);
    const float bh0 = __ldg(bias + 64 + ro), bh1 = __ldg(bias + 64 + ro + 8);
    const int sp0 = band * 256 + n0 + 2 * tig;
    #pragma unroll
    for (int nt = 0; nt < 8; nt++) {
        #pragma unroll
        for (int h = 0; h < 2; h++) {
            const int oc = ro + 8 * h;
            const float bg = h ? bg1 : bg0, bh = h ? bh1 : bh0;
            float gv0 = acc[0][nt][2*h]     + bg;
            float gv1 = acc[0][nt][2*h + 1] + bg;
            float hv0 = acc[1][nt][2*h]     + bh;
            float hv1 = acc[1][nt][2*h + 1] + bh;
            float z0 = sigm(gv0), z1 = sigm(gv1);
            float q0 = (hv0 >= 0.f) ? hv0 + 0.5f : sigm(hv0);
            float q1 = (hv1 >= 0.f) ? hv1 + 0.5f : sigm(hv1);
            int off = ((n * 64 + oc) << 10) + sp0 + nt * 8;
            *(float2*)(Aout + off) = make_float2(1.f - z0, 1.f - z1);
            *(float2*)(Bout + off) = make_float2(z0 * q0, z1 * q1);
        }
    }
}

// Sequential minGRU scan over S=64 (HBM-bound)
__global__ void __launch_bounds__(256)
scan_k(const float* __restrict__ A, const float* __restrict__ Bv,
       float* __restrict__ out, float* __restrict__ hlast)
{
    int idx = blockIdx.x * blockDim.x + threadIdx.x;
    int b = idx >> 16, chw = idx & 65535;
    size_t base = (size_t)(b << 6) * PLANE + chw;
    float h = 0.5f;
    #pragma unroll 8
    for (int t = 0; t < 64; t++) {
        size_t off = base + (size_t)t * PLANE;
        h = fmaf(A[off], h, Bv[off]);
        out[off] = h;
    }
    hlast[idx] = h;
}

extern "C" void kernel_launch(void* const* d_in, const int* in_sizes, int n_in,
                              void* d_out, int out_size) {
    const float* x  = (const float*)d_in[0];
    const float* w1 = (const float*)d_in[1];
    const float* b1 = (const float*)d_in[2];
    const float* w2 = (const float*)d_in[3];
    const float* b2 = (const float*)d_in[4];
    float* out = (float*)d_out;

    float *pA, *pB, *pO1, *pH;
    uint32_t *pW1, *pW2;
    cudaGetSymbolAddress((void**)&pA,  g_A);
    cudaGetSymbolAddress((void**)&pB,  g_B);
    cudaGetSymbolAddress((void**)&pO1, g_O1);
    cudaGetSymbolAddress((void**)&pH,  g_hdump);
    cudaGetSymbolAddress((void**)&pW1, g_Wpk1);
    cudaGetSymbolAddress((void**)&pW2, g_Wpk2);

    const int SMEM32 = 4608 * 4 + 32 * 360 * 4;   // 64512
    const int SMEM64 = 4608 * 4 + 64 * 360 * 4;   // 110592
    cudaFuncSetAttribute(conv_mma<32>, cudaFuncAttributeMaxDynamicSharedMemorySize, SMEM32);
    cudaFuncSetAttribute(conv_mma<64>, cudaFuncAttributeMaxDynamicSharedMemorySize, SMEM64);

    bool full = (out_size >= TOT + 8 * PLANE);
    float* h1 = full ? (out + TOT)             : pH;
    float* h2 = full ? (out + TOT + 4 * PLANE) : pH;

    pack_w<<<162, 256>>>(w1, pW1, 32);
    pack_w<<<324, 256>>>(w2, pW2, 64);
    conv_mma<32><<<1024, 512, SMEM32>>>(x, pW1, b1, pA, pB);
    scan_k<<<1024, 256>>>(pA, pB, pO1, h1);
    conv_mma<64><<<1024, 512, SMEM64>>>(pO1, pW2, b2, pA, pB);
    scan_k<<<1024, 256>>>(pA, pB, out, h2);
}

// round 4
// speedup vs baseline: 4.0415x; 1.5909x over previous
#include <cuda_runtime.h>
#include <cuda_fp16.h>
#include <math.h>
#include <stdint.h>

#define NIMG  256
#define PLANE 65536
#define TOT   16777216

// Scratch (__device__ globals per allocation rules)
__device__ float    g_A[TOT];
__device__ float    g_B[TOT];
__device__ float    g_O1[TOT];
__device__ float    g_hdump[4*PLANE];
__device__ uint32_t g_Wpk1[9*2304];    // layer1 packed fp16x2 weights [stage32][128oc][18]
__device__ uint32_t g_Wpk2[18*2304];   // layer2

__device__ __forceinline__ float sigm(float x) { return 1.f/(1.f+__expf(-x)); }

// Pre-pack weights to half2 pairs: [stage m(k32)][oc 0..127][kpair 0..15 (+2 pad)]
// k_global = tap*IC + ic ; stage covers k in [m*32, m*32+32)
__global__ void pack_w(const float* __restrict__ w, uint32_t* __restrict__ dst, int IC) {
    int idx = blockIdx.x * 256 + threadIdx.x;
    int total = (IC * 9 / 32) * 2304;
    if (idx >= total) return;
    int m = idx / 2304, rem = idx - m * 2304, oc = rem / 18, kp = rem - oc * 18;
    uint32_t v = 0;
    if (kp < 16) {
        int kg = m * 32 + 2 * kp;
        int tap = kg / IC, ic = kg - tap * IC;
        __half2 h = __floats2half2_rn(w[(oc * IC + ic) * 9 + tap],
                                      w[(oc * IC + ic + 1) * 9 + tap]);
        v = *(uint32_t*)&h;
    }
    dst[idx] = v;
}

// Conv3x3 (pad1) as implicit GEMM via mma.sync m16n8k16 fp16 (f32 accum)
// + fused minGRU epilogue. Grid 1024 = 256 images x 4 bands(8 rows).
// 512 threads = 16 warps; warp tile 32oc x 64px; all weights smem-resident.
template<int IC>
__global__ void __launch_bounds__(512, 1)
conv_mma(const float* __restrict__ xin, const uint32_t* __restrict__ wpk,
         const float* __restrict__ bias,
         float* __restrict__ Aout, float* __restrict__ Bout)
{
    extern __shared__ uint32_t sm[];
    constexpr int NST = IC * 9 / 32;           // k32 stages (9 / 18)
    uint32_t* ws    = sm;                      // NST*2304 u32
    uint32_t* tile2 = sm + NST * 2304;         // [IC/2][10][36] half2

    const int tid = threadIdx.x;
    const int wv = tid >> 5, lane = tid & 31;
    const int g = lane >> 2, tig = lane & 3;
    const int mw = wv & 3, nw = wv >> 2;
    const int n0 = nw * 64;
    const int blk = blockIdx.x, band = blk & 3, n = blk >> 2, r0 = band * 8;
    const int ro = mw * 16 + g;

    // All weight stages -> smem (L2-hot float4 copy)
    {
        const float4* src = (const float4*)wpk;
        float4* d4 = (float4*)ws;
        for (int i = tid; i < NST * 576; i += 512) d4[i] = src[i];
    }
    // Padded input tile as channel-pair half2: rows r0-1..r0+8, cols -1..33
    for (int idx = tid; idx < (IC / 2) * 360; idx += 512) {
        int icp = idx / 360, rem = idx - icp * 360, r = rem / 36, c = rem - r * 36;
        int gr = r0 + r - 1, gc = c - 1;
        float lo = 0.f, hi = 0.f;
        if ((unsigned)gr < 32u && (unsigned)gc < 32u) {
            int base = ((n * IC + 2 * icp) << 10) + (gr << 5) + gc;
            lo = xin[base];
            hi = xin[base + 1024];
        }
        __half2 h = __floats2half2_rn(lo, hi);
        tile2[idx] = *(uint32_t*)&h;
    }
    __syncthreads();

    float acc[2][8][4];
    #pragma unroll
    for (int f = 0; f < 2; f++)
        #pragma unroll
        for (int nt = 0; nt < 8; nt++)
            #pragma unroll
            for (int j = 0; j < 4; j++) acc[f][nt][j] = 0.f;

    for (int m = 0; m < NST; m++) {
        const uint32_t* wrow = ws + m * 2304;
        #pragma unroll
        for (int sub = 0; sub < 2; sub++) {
            const int kg0 = m * 32 + sub * 16;
            const int tap = kg0 / IC;
            const int icp0 = (kg0 - tap * IC) >> 1;
            const int dr = tap / 3, dc = tap - dr * 3;
            const int soff = dr * 36 + dc;

            uint32_t a[2][4];
            const int ks = sub * 8 + tig;
            a[0][0] = wrow[ro * 18 + ks];            a[0][1] = wrow[(ro + 8) * 18 + ks];
            a[0][2] = wrow[ro * 18 + ks + 4];        a[0][3] = wrow[(ro + 8) * 18 + ks + 4];
            a[1][0] = wrow[(ro + 64) * 18 + ks];     a[1][1] = wrow[(ro + 72) * 18 + ks];
            a[1][2] = wrow[(ro + 64) * 18 + ks + 4]; a[1][3] = wrow[(ro + 72) * 18 + ks + 4];

            const uint32_t* tb = tile2 + (icp0 + tig) * 360 + soff;
            uint32_t b0[8], b1[8];
            #pragma unroll
            for (int nt = 0; nt < 8; nt++) {
                int px = n0 + nt * 8 + g;
                int sp = (px >> 5) * 36 + (px & 31);
                b0[nt] = tb[sp];
                b1[nt] = tb[sp + 4 * 360];
            }
            #pragma unroll
            for (int f = 0; f < 2; f++)
                #pragma unroll
                for (int nt = 0; nt < 8; nt++)
                    asm volatile(
                        "mma.sync.aligned.m16n8k16.row.col.f32.f16.f16.f32 "
                        "{%0,%1,%2,%3}, {%4,%5,%6,%7}, {%8,%9}, {%0,%1,%2,%3};"
                        : "+f"(acc[f][nt][0]), "+f"(acc[f][nt][1]),
                          "+f"(acc[f][nt][2]), "+f"(acc[f][nt][3])
                        : "r"(a[f][0]), "r"(a[f][1]), "r"(a[f][2]), "r"(a[f][3]),
                          "r"(b0[nt]), "r"(b1[nt]));
        }
    }

    // Fused minGRU epilogue: a = 1 - sigmoid(gate), b = sigmoid(gate) * g(hidden)
    const float bg0 = __ldg(bias + ro),      bg1 = __ldg(bias + ro + 8);
    const float bh0 = __ldg(bias + 64 + ro), bh1 = __ldg(bias + 64 + ro + 8);
    const int sp0 = band * 256 + n0 + 2 * tig;
    #pragma unroll
    for (int nt = 0; nt < 8; nt++) {
        #pragma unroll
        for (int h = 0; h < 2; h++) {
            const int oc = ro + 8 * h;
            const float bg = h ? bg1 : bg0, bh = h ? bh1 : bh0;
            float gv0 = acc[0][nt][2*h]     + bg;
            float gv1 = acc[0][nt][2*h + 1] + bg;
            float hv0 = acc[1][nt][2*h]     + bh;
            float hv1 = acc[1][nt][2*h + 1] + bh;
            float z0 = sigm(gv0), z1 = sigm(gv1);
            float q0 = (hv0 >= 0.f) ? hv0 + 0.5f : sigm(hv0);
            float q1 = (hv1 >= 0.f) ? hv1 + 0.5f : sigm(hv1);
            int off = ((n * 64 + oc) << 10) + sp0 + nt * 8;
            *(float2*)(Aout + off) = make_float2(1.f - z0, 1.f - z1);
            *(float2*)(Bout + off) = make_float2(z0 * q0, z1 * q1);
        }
    }
}

// Sequential minGRU scan over S=64 (HBM-bound, ~70% of peak)
__global__ void __launch_bounds__(256)
scan_k(const float* __restrict__ A, const float* __restrict__ Bv,
       float* __restrict__ out, float* __restrict__ hlast)
{
    int idx = blockIdx.x * blockDim.x + threadIdx.x;
    int b = idx >> 16, chw = idx & 65535;
    size_t base = (size_t)(b << 6) * PLANE + chw;
    float h = 0.5f;
    #pragma unroll 8
    for (int t = 0; t < 64; t++) {
        size_t off = base + (size_t)t * PLANE;
        h = fmaf(A[off], h, Bv[off]);
        out[off] = h;
    }
    hlast[idx] = h;
}

extern "C" void kernel_launch(void* const* d_in, const int* in_sizes, int n_in,
                              void* d_out, int out_size) {
    const float* x  = (const float*)d_in[0];
    const float* w1 = (const float*)d_in[1];
    const float* b1 = (const float*)d_in[2];
    const float* w2 = (const float*)d_in[3];
    const float* b2 = (const float*)d_in[4];
    float* out = (float*)d_out;

    float *pA, *pB, *pO1, *pH;
    uint32_t *pW1, *pW2;
    cudaGetSymbolAddress((void**)&pA,  g_A);
    cudaGetSymbolAddress((void**)&pB,  g_B);
    cudaGetSymbolAddress((void**)&pO1, g_O1);
    cudaGetSymbolAddress((void**)&pH,  g_hdump);
    cudaGetSymbolAddress((void**)&pW1, g_Wpk1);
    cudaGetSymbolAddress((void**)&pW2, g_Wpk2);

    const int SMEM32 = (9 * 2304 + 16 * 360) * 4;    // 105984
    const int SMEM64 = (18 * 2304 + 32 * 360) * 4;   // 211968
    cudaFuncSetAttribute(conv_mma<32>, cudaFuncAttributeMaxDynamicSharedMemorySize, SMEM32);
    cudaFuncSetAttribute(conv_mma<64>, cudaFuncAttributeMaxDynamicSharedMemorySize, SMEM64);

    bool full = (out_size >= TOT + 8 * PLANE);
    float* h1 = full ? (out + TOT)             : pH;
    float* h2 = full ? (out + TOT + 4 * PLANE) : pH;

    pack_w<<<81, 256>>>(w1, pW1, 32);
    pack_w<<<162, 256>>>(w2, pW2, 64);
    conv_mma<32><<<1024, 512, SMEM32>>>(x, pW1, b1, pA, pB);
    scan_k<<<1024, 256>>>(pA, pB, pO1, h1);
    conv_mma<64><<<1024, 512, SMEM64>>>(pO1, pW2, b2, pA, pB);
    scan_k<<<1024, 256>>>(pA, pB, out, h2);
}